// round 5
// baseline (speedup 1.0000x reference)
#include <cuda_runtime.h>

// ---------------------------------------------------------------------------
// FFB encoder, fp32 baseline tuned for sm_103a:
//  - register-tiled SMEM GEMMs (128x128 per level, x2)
//  - packed fma.rn.f32x2 (2x fp32 FMA rate on Blackwell; ptxas never emits it)
//  - weights staged per-level into SMEM (L2-resident across the grid)
// ---------------------------------------------------------------------------

#define HID      128
#define LVL      7
#define TP       128      // points per block
#define NTHREADS 256
#define WS       132      // padded SMEM row stride (floats)
#define W0_SINE  56.0f
#define TWO_PIf  6.28318530717958647692f

typedef unsigned long long u64;

__device__ __forceinline__ u64 pk2(float lo, float hi) {
    u64 r;
    asm("mov.b64 %0, {%1, %2};" : "=l"(r)
        : "r"(__float_as_uint(lo)), "r"(__float_as_uint(hi)));
    return r;
}
__device__ __forceinline__ void upk2(u64 v, float& lo, float& hi) {
    unsigned int a, b;
    asm("mov.b64 {%0, %1}, %2;" : "=r"(a), "=r"(b) : "l"(v));
    lo = __uint_as_float(a);
    hi = __uint_as_float(b);
}
__device__ __forceinline__ void fma2(u64& d, u64 a, u64 b) {
    asm("fma.rn.f32x2 %0, %1, %2, %0;" : "+l"(d) : "l"(a), "l"(b));
}

// 256 threads cooperatively copy a 128x128 fp32 weight matrix (row-major,
// rows = output unit h, cols = k) into SMEM with padded stride WS.
__device__ __forceinline__ void load_weight(float* __restrict__ dst,
                                            const float* __restrict__ src,
                                            int tid) {
    const int row  = tid >> 1;
    const int half = (tid & 1) * 64;
    const float4* s = reinterpret_cast<const float4*>(src + row * HID + half);
    float4*       d = reinterpret_cast<float4*>(dst + row * WS + half);
#pragma unroll
    for (int v = 0; v < 16; ++v) d[v] = s[v];
}

// Y[n][h] = sum_k xs[n][k] * ws[h][k] for the thread's 8x8 tile.
// Accumulators are f32x2 pairs: acc[i][j2] = { y(n_i, tc+32*j2), y(n_i, tc+32*j2+16) }
__device__ __forceinline__ void gemm_tile(const float* __restrict__ xs,
                                          const float* __restrict__ ws,
                                          int tr, int tc, u64 acc[8][4]) {
#pragma unroll
    for (int i = 0; i < 8; ++i)
#pragma unroll
        for (int j = 0; j < 4; ++j) acc[i][j] = 0ULL;

#pragma unroll 2
    for (int k = 0; k < HID; k += 4) {
        float a[8][4], b[8][4];
#pragma unroll
        for (int i = 0; i < 8; ++i)
            *reinterpret_cast<float4*>(a[i]) =
                *reinterpret_cast<const float4*>(xs + (tr + 16 * i) * WS + k);
#pragma unroll
        for (int j = 0; j < 8; ++j)
            *reinterpret_cast<float4*>(b[j]) =
                *reinterpret_cast<const float4*>(ws + (tc + 16 * j) * WS + k);
#pragma unroll
        for (int c = 0; c < 4; ++c) {
            u64 b2[4];
#pragma unroll
            for (int j2 = 0; j2 < 4; ++j2)
                b2[j2] = pk2(b[2 * j2][c], b[2 * j2 + 1][c]);
#pragma unroll
            for (int i = 0; i < 8; ++i) {
                u64 aa = pk2(a[i][c], a[i][c]);
#pragma unroll
                for (int j2 = 0; j2 < 4; ++j2) fma2(acc[i][j2], aa, b2[j2]);
            }
        }
    }
}

extern __shared__ float smem[];

__global__ __launch_bounds__(NTHREADS, 1)
void ffb_encoder_kernel(const float* __restrict__ in_pos,
                        const float* __restrict__ grid_feats,
                        const float* __restrict__ ffn_A,
                        const float* __restrict__ ffn_sigma,
                        const float* __restrict__ W0,
                        const float* __restrict__ b0,
                        const float* __restrict__ W_mid,
                        const float* __restrict__ b_mid,
                        const float* __restrict__ W_high,
                        const float* __restrict__ b_high,
                        float* __restrict__ out) {
    float* xs  = smem;                  // TP * WS
    float* ws  = xs + TP * WS;          // HID * WS
    float* gs  = ws + HID * WS;         // TP * 14
    float* As  = gs + TP * 14;          // LVL * 2 * HID (pre-scaled by 2*pi*sigma)
    float* bms = As + LVL * 2 * HID;    // LVL * HID
    float* bhs = bms + LVL * HID;       // LVL * HID
    float* ps  = bhs + LVL * HID;       // TP * 3

    const int tid = threadIdx.x;
    const int n0  = blockIdx.x * TP;
    const int tr  = tid >> 4;   // 0..15, point-group
    const int tc  = tid & 15;   // 0..15, hidden-group

    // ------------------------- setup: stage to SMEM -------------------------
    for (int idx = tid; idx < TP * 14; idx += NTHREADS) {
        int p = idx / 14, c = idx - p * 14;
        gs[idx] = grid_feats[(n0 + p) * 17 + 3 + c];
    }
    for (int idx = tid; idx < TP * 3; idx += NTHREADS) {
        int p = idx / 3, d = idx - p * 3;
        float v = in_pos[(n0 + p) * 3 + d];
        ps[idx]  = v;
        out[(size_t)(n0 + p) * 131 + d] = (v + 1.0f) * 0.5f;   // pos01
    }
    for (int idx = tid; idx < LVL * 2 * HID; idx += NTHREADS) {
        int l = idx / (2 * HID);
        As[idx] = ffn_A[idx] * ffn_sigma[l] * TWO_PIf;
    }
    for (int idx = tid; idx < LVL * HID; idx += NTHREADS) {
        bms[idx] = b_mid[idx];
        bhs[idx] = b_high[idx];
    }
    // stage W0/b0 into ws (temporarily) as [h]{w0,w1,w2,b}
    if (tid < HID) {
        ws[tid * 4 + 0] = W0[tid * 3 + 0];
        ws[tid * 4 + 1] = W0[tid * 3 + 1];
        ws[tid * 4 + 2] = W0[tid * 3 + 2];
        ws[tid * 4 + 3] = b0[tid];
    }
    __syncthreads();

    // ------------------------- first SIREN layer ---------------------------
#pragma unroll
    for (int i = 0; i < 8; ++i) {
        int n = tr + 16 * i;
        float p0 = ps[n * 3 + 0], p1 = ps[n * 3 + 1], p2 = ps[n * 3 + 2];
#pragma unroll
        for (int j = 0; j < 8; ++j) {
            int h = tc + 16 * j;
            const float* w = ws + h * 4;
            float u = fmaf(p0, w[0], fmaf(p1, w[1], fmaf(p2, w[2], w[3])));
            xs[n * WS + h] = __sinf(W0_SINE * u);
        }
    }

    float buf[8][8];
#pragma unroll
    for (int i = 0; i < 8; ++i)
#pragma unroll
        for (int j = 0; j < 8; ++j) buf[i][j] = 0.0f;

    u64 acc[8][4];

    // ------------------------------ level loop -----------------------------
    for (int l = 0; l < LVL; ++l) {
        __syncthreads();                          // prior ws readers done
        load_weight(ws, W_mid + l * HID * HID, tid);
        __syncthreads();

        gemm_tile(xs, ws, tr, tc, acc);           // t = x @ Wm^T
        __syncthreads();                          // all xs reads done

        // x = sin(2*pi*A . g) + sin(56*(t + bm))   (residual), write back
#pragma unroll
        for (int i = 0; i < 8; ++i) {
            int n = tr + 16 * i;
            float g0 = gs[n * 14 + 2 * l];
            float g1 = gs[n * 14 + 2 * l + 1];
#pragma unroll
            for (int j2 = 0; j2 < 4; ++j2) {
                float v0, v1;
                upk2(acc[i][j2], v0, v1);
                int h0 = tc + 32 * j2, h1 = h0 + 16;
                float gr0 = sinf(fmaf(g0, As[(2 * l) * HID + h0],
                                      g1 * As[(2 * l + 1) * HID + h0]));
                float gr1 = sinf(fmaf(g0, As[(2 * l) * HID + h1],
                                      g1 * As[(2 * l + 1) * HID + h1]));
                xs[n * WS + h0] = gr0 + __sinf(W0_SINE * (v0 + bms[l * HID + h0]));
                xs[n * WS + h1] = gr1 + __sinf(W0_SINE * (v1 + bms[l * HID + h1]));
            }
        }
        __syncthreads();                          // xs writes visible, ws free
        load_weight(ws, W_high + l * HID * HID, tid);
        __syncthreads();

        gemm_tile(xs, ws, tr, tc, acc);           // u = x @ Wh^T

        // buf += sin(56*(u + bh))   (stays in registers across levels)
#pragma unroll
        for (int i = 0; i < 8; ++i) {
#pragma unroll
            for (int j2 = 0; j2 < 4; ++j2) {
                float v0, v1;
                upk2(acc[i][j2], v0, v1);
                int h0 = tc + 32 * j2, h1 = h0 + 16;
                buf[i][2 * j2]     += __sinf(W0_SINE * (v0 + bhs[l * HID + h0]));
                buf[i][2 * j2 + 1] += __sinf(W0_SINE * (v1 + bhs[l * HID + h1]));
            }
        }
        // top-of-loop __syncthreads() orders ws reuse for next level
    }

    // ------------------------------- epilogue ------------------------------
    const float inv = 1.0f / 7.0f;
#pragma unroll
    for (int i = 0; i < 8; ++i) {
        size_t n = (size_t)(n0 + tr + 16 * i);
#pragma unroll
        for (int j = 0; j < 8; ++j) {
            int h = tc + 16 * j;
            out[n * 131 + 3 + h] = buf[i][j] * inv;
        }
    }
}

extern "C" void kernel_launch(void* const* d_in, const int* in_sizes, int n_in,
                              void* d_out, int out_size) {
    const float* in_pos     = (const float*)d_in[0];
    const float* grid_feats = (const float*)d_in[1];
    const float* ffn_A      = (const float*)d_in[2];
    const float* ffn_sigma  = (const float*)d_in[3];
    const float* W0         = (const float*)d_in[4];
    const float* b0         = (const float*)d_in[5];
    const float* W_mid      = (const float*)d_in[6];
    const float* b_mid      = (const float*)d_in[7];
    const float* W_high     = (const float*)d_in[8];
    const float* b_high     = (const float*)d_in[9];
    float* out = (float*)d_out;

    const int N       = in_sizes[0] / 3;   // 131072
    const int nblocks = N / TP;            // 1024

    const size_t smem_bytes =
        (size_t)(TP * WS + HID * WS + TP * 14 + LVL * 2 * HID +
                 2 * LVL * HID + TP * 3) * sizeof(float);   // ~158 KB

    // Idempotent, called every time (deterministic; legal during graph capture).
    cudaFuncSetAttribute(ffb_encoder_kernel,
                         cudaFuncAttributeMaxDynamicSharedMemorySize,
                         (int)smem_bytes);

    ffb_encoder_kernel<<<nblocks, NTHREADS, smem_bytes>>>(
        in_pos, grid_feats, ffn_A, ffn_sigma, W0, b0,
        W_mid, b_mid, W_high, b_high, out);
}

// round 6
// speedup vs baseline: 1.0013x; 1.0013x over previous
#include <cuda_runtime.h>

// ---------------------------------------------------------------------------
// FFB encoder, fp32 baseline tuned for sm_103a:
//  - register-tiled SMEM GEMMs (128x128 per level, x2)
//  - packed fma.rn.f32x2 (2x fp32 FMA rate on Blackwell; ptxas never emits it)
//  - weights staged per-level into SMEM (L2-resident across the grid)
// ---------------------------------------------------------------------------

#define HID      128
#define LVL      7
#define TP       128      // points per block
#define NTHREADS 256
#define WS       132      // padded SMEM row stride (floats)
#define W0_SINE  56.0f
#define TWO_PIf  6.28318530717958647692f

typedef unsigned long long u64;

__device__ __forceinline__ u64 pk2(float lo, float hi) {
    u64 r;
    asm("mov.b64 %0, {%1, %2};" : "=l"(r)
        : "r"(__float_as_uint(lo)), "r"(__float_as_uint(hi)));
    return r;
}
__device__ __forceinline__ void upk2(u64 v, float& lo, float& hi) {
    unsigned int a, b;
    asm("mov.b64 {%0, %1}, %2;" : "=r"(a), "=r"(b) : "l"(v));
    lo = __uint_as_float(a);
    hi = __uint_as_float(b);
}
__device__ __forceinline__ void fma2(u64& d, u64 a, u64 b) {
    asm("fma.rn.f32x2 %0, %1, %2, %0;" : "+l"(d) : "l"(a), "l"(b));
}

// 256 threads cooperatively copy a 128x128 fp32 weight matrix (row-major,
// rows = output unit h, cols = k) into SMEM with padded stride WS.
__device__ __forceinline__ void load_weight(float* __restrict__ dst,
                                            const float* __restrict__ src,
                                            int tid) {
    const int row  = tid >> 1;
    const int half = (tid & 1) * 64;
    const float4* s = reinterpret_cast<const float4*>(src + row * HID + half);
    float4*       d = reinterpret_cast<float4*>(dst + row * WS + half);
#pragma unroll
    for (int v = 0; v < 16; ++v) d[v] = s[v];
}

// Y[n][h] = sum_k xs[n][k] * ws[h][k] for the thread's 8x8 tile.
// Accumulators are f32x2 pairs: acc[i][j2] = { y(n_i, tc+32*j2), y(n_i, tc+32*j2+16) }
__device__ __forceinline__ void gemm_tile(const float* __restrict__ xs,
                                          const float* __restrict__ ws,
                                          int tr, int tc, u64 acc[8][4]) {
#pragma unroll
    for (int i = 0; i < 8; ++i)
#pragma unroll
        for (int j = 0; j < 4; ++j) acc[i][j] = 0ULL;

#pragma unroll 2
    for (int k = 0; k < HID; k += 4) {
        float a[8][4], b[8][4];
#pragma unroll
        for (int i = 0; i < 8; ++i)
            *reinterpret_cast<float4*>(a[i]) =
                *reinterpret_cast<const float4*>(xs + (tr + 16 * i) * WS + k);
#pragma unroll
        for (int j = 0; j < 8; ++j)
            *reinterpret_cast<float4*>(b[j]) =
                *reinterpret_cast<const float4*>(ws + (tc + 16 * j) * WS + k);
#pragma unroll
        for (int c = 0; c < 4; ++c) {
            u64 b2[4];
#pragma unroll
            for (int j2 = 0; j2 < 4; ++j2)
                b2[j2] = pk2(b[2 * j2][c], b[2 * j2 + 1][c]);
#pragma unroll
            for (int i = 0; i < 8; ++i) {
                u64 aa = pk2(a[i][c], a[i][c]);
#pragma unroll
                for (int j2 = 0; j2 < 4; ++j2) fma2(acc[i][j2], aa, b2[j2]);
            }
        }
    }
}

extern __shared__ float smem[];

__global__ __launch_bounds__(NTHREADS, 1)
void ffb_encoder_kernel(const float* __restrict__ in_pos,
                        const float* __restrict__ grid_feats,
                        const float* __restrict__ ffn_A,
                        const float* __restrict__ ffn_sigma,
                        const float* __restrict__ W0,
                        const float* __restrict__ b0,
                        const float* __restrict__ W_mid,
                        const float* __restrict__ b_mid,
                        const float* __restrict__ W_high,
                        const float* __restrict__ b_high,
                        float* __restrict__ out) {
    float* xs  = smem;                  // TP * WS
    float* ws  = xs + TP * WS;          // HID * WS
    float* gs  = ws + HID * WS;         // TP * 14
    float* As  = gs + TP * 14;          // LVL * 2 * HID (pre-scaled by 2*pi*sigma)
    float* bms = As + LVL * 2 * HID;    // LVL * HID
    float* bhs = bms + LVL * HID;       // LVL * HID
    float* ps  = bhs + LVL * HID;       // TP * 3

    const int tid = threadIdx.x;
    const int n0  = blockIdx.x * TP;
    const int tr  = tid >> 4;   // 0..15, point-group
    const int tc  = tid & 15;   // 0..15, hidden-group

    // ------------------------- setup: stage to SMEM -------------------------
    for (int idx = tid; idx < TP * 14; idx += NTHREADS) {
        int p = idx / 14, c = idx - p * 14;
        gs[idx] = grid_feats[(n0 + p) * 17 + 3 + c];
    }
    for (int idx = tid; idx < TP * 3; idx += NTHREADS) {
        int p = idx / 3, d = idx - p * 3;
        float v = in_pos[(n0 + p) * 3 + d];
        ps[idx]  = v;
        out[(size_t)(n0 + p) * 131 + d] = (v + 1.0f) * 0.5f;   // pos01
    }
    for (int idx = tid; idx < LVL * 2 * HID; idx += NTHREADS) {
        int l = idx / (2 * HID);
        As[idx] = ffn_A[idx] * ffn_sigma[l] * TWO_PIf;
    }
    for (int idx = tid; idx < LVL * HID; idx += NTHREADS) {
        bms[idx] = b_mid[idx];
        bhs[idx] = b_high[idx];
    }
    // stage W0/b0 into ws (temporarily) as [h]{w0,w1,w2,b}
    if (tid < HID) {
        ws[tid * 4 + 0] = W0[tid * 3 + 0];
        ws[tid * 4 + 1] = W0[tid * 3 + 1];
        ws[tid * 4 + 2] = W0[tid * 3 + 2];
        ws[tid * 4 + 3] = b0[tid];
    }
    __syncthreads();

    // ------------------------- first SIREN layer ---------------------------
#pragma unroll
    for (int i = 0; i < 8; ++i) {
        int n = tr + 16 * i;
        float p0 = ps[n * 3 + 0], p1 = ps[n * 3 + 1], p2 = ps[n * 3 + 2];
#pragma unroll
        for (int j = 0; j < 8; ++j) {
            int h = tc + 16 * j;
            const float* w = ws + h * 4;
            float u = fmaf(p0, w[0], fmaf(p1, w[1], fmaf(p2, w[2], w[3])));
            xs[n * WS + h] = __sinf(W0_SINE * u);
        }
    }

    float buf[8][8];
#pragma unroll
    for (int i = 0; i < 8; ++i)
#pragma unroll
        for (int j = 0; j < 8; ++j) buf[i][j] = 0.0f;

    u64 acc[8][4];

    // ------------------------------ level loop -----------------------------
    for (int l = 0; l < LVL; ++l) {
        __syncthreads();                          // prior ws readers done
        load_weight(ws, W_mid + l * HID * HID, tid);
        __syncthreads();

        gemm_tile(xs, ws, tr, tc, acc);           // t = x @ Wm^T
        __syncthreads();                          // all xs reads done

        // x = sin(2*pi*A . g) + sin(56*(t + bm))   (residual), write back
#pragma unroll
        for (int i = 0; i < 8; ++i) {
            int n = tr + 16 * i;
            float g0 = gs[n * 14 + 2 * l];
            float g1 = gs[n * 14 + 2 * l + 1];
#pragma unroll
            for (int j2 = 0; j2 < 4; ++j2) {
                float v0, v1;
                upk2(acc[i][j2], v0, v1);
                int h0 = tc + 32 * j2, h1 = h0 + 16;
                float gr0 = sinf(fmaf(g0, As[(2 * l) * HID + h0],
                                      g1 * As[(2 * l + 1) * HID + h0]));
                float gr1 = sinf(fmaf(g0, As[(2 * l) * HID + h1],
                                      g1 * As[(2 * l + 1) * HID + h1]));
                xs[n * WS + h0] = gr0 + __sinf(W0_SINE * (v0 + bms[l * HID + h0]));
                xs[n * WS + h1] = gr1 + __sinf(W0_SINE * (v1 + bms[l * HID + h1]));
            }
        }
        __syncthreads();                          // xs writes visible, ws free
        load_weight(ws, W_high + l * HID * HID, tid);
        __syncthreads();

        gemm_tile(xs, ws, tr, tc, acc);           // u = x @ Wh^T

        // buf += sin(56*(u + bh))   (stays in registers across levels)
#pragma unroll
        for (int i = 0; i < 8; ++i) {
#pragma unroll
            for (int j2 = 0; j2 < 4; ++j2) {
                float v0, v1;
                upk2(acc[i][j2], v0, v1);
                int h0 = tc + 32 * j2, h1 = h0 + 16;
                buf[i][2 * j2]     += __sinf(W0_SINE * (v0 + bhs[l * HID + h0]));
                buf[i][2 * j2 + 1] += __sinf(W0_SINE * (v1 + bhs[l * HID + h1]));
            }
        }
        // top-of-loop __syncthreads() orders ws reuse for next level
    }

    // ------------------------------- epilogue ------------------------------
    const float inv = 1.0f / 7.0f;
#pragma unroll
    for (int i = 0; i < 8; ++i) {
        size_t n = (size_t)(n0 + tr + 16 * i);
#pragma unroll
        for (int j = 0; j < 8; ++j) {
            int h = tc + 16 * j;
            out[n * 131 + 3 + h] = buf[i][j] * inv;
        }
    }
}

extern "C" void kernel_launch(void* const* d_in, const int* in_sizes, int n_in,
                              void* d_out, int out_size) {
    const float* in_pos     = (const float*)d_in[0];
    const float* grid_feats = (const float*)d_in[1];
    const float* ffn_A      = (const float*)d_in[2];
    const float* ffn_sigma  = (const float*)d_in[3];
    const float* W0         = (const float*)d_in[4];
    const float* b0         = (const float*)d_in[5];
    const float* W_mid      = (const float*)d_in[6];
    const float* b_mid      = (const float*)d_in[7];
    const float* W_high     = (const float*)d_in[8];
    const float* b_high     = (const float*)d_in[9];
    float* out = (float*)d_out;

    const int N       = in_sizes[0] / 3;   // 131072
    const int nblocks = N / TP;            // 1024

    const size_t smem_bytes =
        (size_t)(TP * WS + HID * WS + TP * 14 + LVL * 2 * HID +
                 2 * LVL * HID + TP * 3) * sizeof(float);   // ~158 KB

    // Idempotent, called every time (deterministic; legal during graph capture).
    cudaFuncSetAttribute(ffb_encoder_kernel,
                         cudaFuncAttributeMaxDynamicSharedMemorySize,
                         (int)smem_bytes);

    ffb_encoder_kernel<<<nblocks, NTHREADS, smem_bytes>>>(
        in_pos, grid_feats, ffn_A, ffn_sigma, W0, b0,
        W_mid, b_mid, W_high, b_high, out);
}

// round 7
// speedup vs baseline: 1.8060x; 1.8037x over previous
#include <cuda_runtime.h>

// ---------------------------------------------------------------------------
// FFB encoder v2 for sm_103a:
//  - 512 threads (4 warps/SMSP) for latency hiding; buf accumulator in SMEM
//  - point-paired f32x2 accumulators: A operand is a direct LDS.64 pair from
//    a transposed activation buffer xst[k][n] (written by us -> free transpose)
//  - only B-operand dup packs remain (4/k/thread) on the alu pipe
//  - weights flat [h][k]: staging is a coalesced memcpy, B loads broadcast
//  - Cody-Waite + deg-11 poly sin for the large-argument grid branch
// ---------------------------------------------------------------------------

#define HID  128
#define LVL  7
#define TP   128      // points per block
#define NT   512
#define WSX  132      // xst row stride (floats), k rows x n cols
#define BS   132      // buf row stride (floats), n rows x h cols
#define W0S  56.0f
#define TWO_PIf 6.28318530717958647692f

typedef unsigned long long u64;

__device__ __forceinline__ u64 pk2(float lo, float hi) {
    u64 r;
    asm("mov.b64 %0, {%1, %2};" : "=l"(r)
        : "r"(__float_as_uint(lo)), "r"(__float_as_uint(hi)));
    return r;
}
__device__ __forceinline__ void upk2(u64 v, float& lo, float& hi) {
    unsigned int a, b;
    asm("mov.b64 {%0, %1}, %2;" : "=r"(a), "=r"(b) : "l"(v));
    lo = __uint_as_float(a);
    hi = __uint_as_float(b);
}
__device__ __forceinline__ void fma2(u64& d, u64 a, u64 b) {
    asm("fma.rn.f32x2 %0, %1, %2, %0;" : "+l"(d) : "l"(a), "l"(b));
}

// Accurate-enough sin for |x| <~ 1e3: round-to-nearest pi reduction with a
// 2-term Cody-Waite split, deg-11 odd polynomial on [-pi/2, pi/2]. ~1e-7 abs.
__device__ __forceinline__ float cw_sin(float x) {
    const float INV_PI = 0.318309886183790672f;
    const float PI_HI  = 3.14159274101257324f;    // fl(pi)
    const float PI_LO  = -8.74227765734758577e-8f; // pi - PI_HI
    int   ni = __float2int_rn(x * INV_PI);
    float nf = __int2float_rn(ni);
    float r  = fmaf(nf, -PI_HI, x);
    r        = fmaf(nf, -PI_LO, r);
    float s2 = r * r;
    float p  = -2.50521084e-8f;
    p = fmaf(p, s2,  2.75573192e-6f);
    p = fmaf(p, s2, -1.98412698e-4f);
    p = fmaf(p, s2,  8.33333333e-3f);
    p = fmaf(p, s2, -1.66666667e-1f);
    float res = fmaf(r * s2, p, r);
    return __int_as_float(__float_as_int(res) ^ (ni << 31));  // sign flip if odd
}

// Flat copy of a 128x128 fp32 weight matrix (row-major [h][k]) into SMEM.
// 512 threads x 8 float4 each; coalesced LDG.128 + conflict-free STS.128.
__device__ __forceinline__ void load_weight(float* __restrict__ dst,
                                            const float* __restrict__ src,
                                            int tid) {
    const float4* s = reinterpret_cast<const float4*>(src);
    float4*       d = reinterpret_cast<float4*>(dst);
#pragma unroll
    for (int v = 0; v < 8; ++v) d[tid + v * NT] = s[tid + v * NT];
}

// y[n][h] = sum_k xst[k][n] * ws[h*128+k] for the thread's 8pt x 4h tile.
// acc[i][j] = { y(nb+32i, hb+j), y(nb+32i+1, hb+j) }  (point-paired f32x2)
__device__ __forceinline__ void gemm_tile(const float* __restrict__ xst,
                                          const float* __restrict__ ws,
                                          int nb, int hb, u64 acc[4][4]) {
#pragma unroll
    for (int i = 0; i < 4; ++i)
#pragma unroll
        for (int j = 0; j < 4; ++j) acc[i][j] = 0ULL;

#pragma unroll 2
    for (int k = 0; k < HID; k += 4) {
        float bf[4][4];
#pragma unroll
        for (int j = 0; j < 4; ++j)
            *reinterpret_cast<float4*>(bf[j]) =
                *reinterpret_cast<const float4*>(ws + (hb + j) * HID + k);
#pragma unroll
        for (int c = 0; c < 4; ++c) {
            const float* row = xst + (k + c) * WSX + nb;
            u64 a0 = *reinterpret_cast<const u64*>(row);
            u64 a1 = *reinterpret_cast<const u64*>(row + 32);
            u64 a2 = *reinterpret_cast<const u64*>(row + 64);
            u64 a3 = *reinterpret_cast<const u64*>(row + 96);
            u64 bb[4];
#pragma unroll
            for (int j = 0; j < 4; ++j) bb[j] = pk2(bf[j][c], bf[j][c]);
#pragma unroll
            for (int j = 0; j < 4; ++j) {
                fma2(acc[0][j], a0, bb[j]);
                fma2(acc[1][j], a1, bb[j]);
                fma2(acc[2][j], a2, bb[j]);
                fma2(acc[3][j], a3, bb[j]);
            }
        }
    }
}

extern __shared__ float smem[];

__global__ __launch_bounds__(NT, 1)
void ffb_encoder_kernel(const float* __restrict__ in_pos,
                        const float* __restrict__ grid_feats,
                        const float* __restrict__ ffn_A,
                        const float* __restrict__ ffn_sigma,
                        const float* __restrict__ W0,
                        const float* __restrict__ b0,
                        const float* __restrict__ W_mid,
                        const float* __restrict__ b_mid,
                        const float* __restrict__ W_high,
                        const float* __restrict__ b_high,
                        float* __restrict__ out) {
    float* xst = smem;                   // HID * WSX   activations, [k][n]
    float* ws  = xst + HID * WSX;        // HID * HID   weights, flat [h][k]
    float* buf = ws + HID * HID;         // TP * BS     high-freq acc, [n][h]
    float* gs  = buf + TP * BS;          // TP * 14     grid feats
    float* As  = gs + TP * 14;           // LVL*2*HID   2*pi*sigma*A
    float* bms = As + LVL * 2 * HID;     // LVL * HID
    float* bhs = bms + LVL * HID;        // LVL * HID
    float* ps  = bhs + LVL * HID;        // TP * 3      positions

    const int tid = threadIdx.x;
    const int n0  = blockIdx.x * TP;
    const int tr  = tid & 15;            // 0..15 point-pair group
    const int tc  = tid >> 4;            // 0..31 hidden group
    const int nb  = 2 * tr;              // base point (pairs at nb+32i)
    const int hb  = 4 * tc;              // base hidden

    // ------------------------- setup: stage to SMEM -------------------------
    for (int idx = tid; idx < TP * 14; idx += NT) {
        int p = idx / 14, c = idx - p * 14;
        gs[idx] = grid_feats[(n0 + p) * 17 + 3 + c];
    }
    for (int idx = tid; idx < TP * 3; idx += NT) {
        int p = idx / 3, d = idx - p * 3;
        float v = in_pos[(n0 + p) * 3 + d];
        ps[idx] = v;
        out[(size_t)(n0 + p) * 131 + d] = (v + 1.0f) * 0.5f;   // pos01
    }
    for (int idx = tid; idx < LVL * 2 * HID; idx += NT) {
        int l = idx / (2 * HID);
        As[idx] = ffn_A[idx] * ffn_sigma[l] * TWO_PIf;
    }
    for (int idx = tid; idx < LVL * HID; idx += NT) {
        bms[idx] = b_mid[idx];
        bhs[idx] = b_high[idx];
    }
    for (int idx = tid; idx < TP * BS; idx += NT) buf[idx] = 0.0f;
    // stage W0/b0 temporarily into ws as [h]{w0,w1,w2,b}
    if (tid < HID) {
        ws[tid * 4 + 0] = W0[tid * 3 + 0];
        ws[tid * 4 + 1] = W0[tid * 3 + 1];
        ws[tid * 4 + 2] = W0[tid * 3 + 2];
        ws[tid * 4 + 3] = b0[tid];
    }
    __syncthreads();

    // ---------------- first SIREN layer, written transposed ----------------
#pragma unroll
    for (int j = 0; j < 4; ++j) {
        int h = hb + j;
        float w0 = ws[h * 4 + 0], w1 = ws[h * 4 + 1];
        float w2 = ws[h * 4 + 2], bb = ws[h * 4 + 3];
#pragma unroll
        for (int i = 0; i < 4; ++i) {
            int n = nb + 32 * i;
            float ue = fmaf(w2, ps[n * 3 + 2],
                       fmaf(w1, ps[n * 3 + 1], fmaf(w0, ps[n * 3 + 0], bb)));
            float uo = fmaf(w2, ps[n * 3 + 5],
                       fmaf(w1, ps[n * 3 + 4], fmaf(w0, ps[n * 3 + 3], bb)));
            *reinterpret_cast<u64*>(xst + h * WSX + n) =
                pk2(__sinf(W0S * ue), __sinf(W0S * uo));
        }
    }

    u64 acc[4][4];

    // ------------------------------ level loop -----------------------------
    for (int l = 0; l < LVL; ++l) {
        __syncthreads();                              // prior ws readers done
        load_weight(ws, W_mid + l * HID * HID, tid);
        __syncthreads();

        gemm_tile(xst, ws, nb, hb, acc);              // t = x @ Wm^T
        __syncthreads();                              // xs/ws reads done

        load_weight(ws, W_high + l * HID * HID, tid); // overlap with epilogue

        float A0[4], A1[4], bm4[4];
#pragma unroll
        for (int j = 0; j < 4; ++j) {
            A0[j]  = As[(2 * l) * HID + hb + j];
            A1[j]  = As[(2 * l + 1) * HID + hb + j];
            bm4[j] = bms[l * HID + hb + j];
        }
#pragma unroll
        for (int i = 0; i < 4; ++i) {
            int n = nb + 32 * i;
            float2 ge = *reinterpret_cast<const float2*>(gs + n * 14 + 2 * l);
            float2 go = *reinterpret_cast<const float2*>(gs + (n + 1) * 14 + 2 * l);
#pragma unroll
            for (int j = 0; j < 4; ++j) {
                float ve, vo;
                upk2(acc[i][j], ve, vo);
                float se = cw_sin(fmaf(ge.x, A0[j], ge.y * A1[j]));
                float so = cw_sin(fmaf(go.x, A0[j], go.y * A1[j]));
                float xe = se + __sinf(W0S * (ve + bm4[j]));
                float xo = so + __sinf(W0S * (vo + bm4[j]));
                *reinterpret_cast<u64*>(xst + (hb + j) * WSX + n) = pk2(xe, xo);
            }
        }
        __syncthreads();                              // xst + ws(high) ready

        gemm_tile(xst, ws, nb, hb, acc);              // u = x @ Wh^T

        // buf += sin(56*(u + bh)) — thread-private SMEM cells, no barrier
        float bh4[4];
#pragma unroll
        for (int j = 0; j < 4; ++j) bh4[j] = bhs[l * HID + hb + j];
#pragma unroll
        for (int i = 0; i < 4; ++i) {
            int n = nb + 32 * i;
            float4* pe = reinterpret_cast<float4*>(buf + n * BS + hb);
            float4* po = reinterpret_cast<float4*>(buf + (n + 1) * BS + hb);
            float4 ve4 = *pe, vo4 = *po;
            float ve, vo;
            upk2(acc[i][0], ve, vo);
            ve4.x += __sinf(W0S * (ve + bh4[0]));
            vo4.x += __sinf(W0S * (vo + bh4[0]));
            upk2(acc[i][1], ve, vo);
            ve4.y += __sinf(W0S * (ve + bh4[1]));
            vo4.y += __sinf(W0S * (vo + bh4[1]));
            upk2(acc[i][2], ve, vo);
            ve4.z += __sinf(W0S * (ve + bh4[2]));
            vo4.z += __sinf(W0S * (vo + bh4[2]));
            upk2(acc[i][3], ve, vo);
            ve4.w += __sinf(W0S * (ve + bh4[3]));
            vo4.w += __sinf(W0S * (vo + bh4[3]));
            *pe = ve4;
            *po = vo4;
        }
    }

    // ------------------------------- epilogue -------------------------------
    __syncthreads();
    const float inv = 1.0f / 7.0f;
    for (int idx = tid; idx < TP * HID; idx += NT) {
        int n = idx >> 7, h = idx & 127;
        out[(size_t)(n0 + n) * 131 + 3 + h] = buf[n * BS + h] * inv;
    }
}

extern "C" void kernel_launch(void* const* d_in, const int* in_sizes, int n_in,
                              void* d_out, int out_size) {
    const float* in_pos     = (const float*)d_in[0];
    const float* grid_feats = (const float*)d_in[1];
    const float* ffn_A      = (const float*)d_in[2];
    const float* ffn_sigma  = (const float*)d_in[3];
    const float* W0         = (const float*)d_in[4];
    const float* b0         = (const float*)d_in[5];
    const float* W_mid      = (const float*)d_in[6];
    const float* b_mid      = (const float*)d_in[7];
    const float* W_high     = (const float*)d_in[8];
    const float* b_high     = (const float*)d_in[9];
    float* out = (float*)d_out;

    const int N       = in_sizes[0] / 3;   // 131072
    const int nblocks = N / TP;            // 1024

    const size_t smem_bytes =
        (size_t)(HID * WSX + HID * HID + TP * BS + TP * 14 +
                 LVL * 2 * HID + 2 * LVL * HID + TP * 3) * sizeof(float); // ~218.5 KB

    cudaFuncSetAttribute(ffb_encoder_kernel,
                         cudaFuncAttributeMaxDynamicSharedMemorySize,
                         (int)smem_bytes);

    ffb_encoder_kernel<<<nblocks, NT, smem_bytes>>>(
        in_pos, grid_feats, ffn_A, ffn_sigma, W0, b0,
        W_mid, b_mid, W_high, b_high, out);
}

// round 8
// speedup vs baseline: 1.8962x; 1.0499x over previous
#include <cuda_runtime.h>

// ---------------------------------------------------------------------------
// FFB encoder v3 for sm_103a — crossbar-minimal LDS mapping:
//  - warp = 8-h slab over all 128 points; lane owns 4 consecutive points
//  - A operand: one LDS.128/k, all lanes distinct+contiguous (4 wf, the
//    unique-byte floor), loaded as ulonglong2 -> zero A-side packs
//  - B operand: warp-uniform broadcast LDS.128 per (j,k4) -> 1 wf each
//  - xst stores / buf updates: lane-contiguous 128-bit, conflict-free
//  - point-paired fma.rn.f32x2 accumulators (16 u64/thread)
// ---------------------------------------------------------------------------

#define HID  128
#define LVL  7
#define TP   128      // points per block
#define NT   512
#define WSX  132      // row stride (floats) for xst[k][n] and buf[h][n]
#define W0S  56.0f
#define TWO_PIf 6.28318530717958647692f

typedef unsigned long long u64;

__device__ __forceinline__ u64 pk2(float lo, float hi) {
    u64 r;
    asm("mov.b64 %0, {%1, %2};" : "=l"(r)
        : "r"(__float_as_uint(lo)), "r"(__float_as_uint(hi)));
    return r;
}
__device__ __forceinline__ void upk2(u64 v, float& lo, float& hi) {
    unsigned int a, b;
    asm("mov.b64 {%0, %1}, %2;" : "=r"(a), "=r"(b) : "l"(v));
    lo = __uint_as_float(a);
    hi = __uint_as_float(b);
}
__device__ __forceinline__ void fma2(u64& d, u64 a, u64 b) {
    asm("fma.rn.f32x2 %0, %1, %2, %0;" : "+l"(d) : "l"(a), "l"(b));
}

// sin for |x| <~ 1e3: RN pi-reduction (2-term Cody-Waite), deg-11 odd poly.
__device__ __forceinline__ float cw_sin(float x) {
    const float INV_PI = 0.318309886183790672f;
    const float PI_HI  = 3.14159274101257324f;
    const float PI_LO  = -8.74227765734758577e-8f;
    int   ni = __float2int_rn(x * INV_PI);
    float nf = __int2float_rn(ni);
    float r  = fmaf(nf, -PI_HI, x);
    r        = fmaf(nf, -PI_LO, r);
    float s2 = r * r;
    float p  = -2.50521084e-8f;
    p = fmaf(p, s2,  2.75573192e-6f);
    p = fmaf(p, s2, -1.98412698e-4f);
    p = fmaf(p, s2,  8.33333333e-3f);
    p = fmaf(p, s2, -1.66666667e-1f);
    float res = fmaf(r * s2, p, r);
    return __int_as_float(__float_as_int(res) ^ (ni << 31));
}

// Flat copy of a 128x128 fp32 weight matrix (row-major [h][k]) into SMEM.
__device__ __forceinline__ void load_weight(float* __restrict__ dst,
                                            const float* __restrict__ src,
                                            int tid) {
    const float4* s = reinterpret_cast<const float4*>(src);
    float4*       d = reinterpret_cast<float4*>(dst);
#pragma unroll
    for (int v = 0; v < 8; ++v) d[tid + v * NT] = s[tid + v * NT];
}

// y[n][h] = sum_k xst[k][n] * ws[h*128+k] for this thread's 4pt x 8h tile.
// acc[p][j] = { y(pb+2p, hb+j), y(pb+2p+1, hb+j) }
__device__ __forceinline__ void gemm_tile(const float* __restrict__ xst,
                                          const float* __restrict__ ws,
                                          int pb, int hb, u64 acc[2][8]) {
#pragma unroll
    for (int p = 0; p < 2; ++p)
#pragma unroll
        for (int j = 0; j < 8; ++j) acc[p][j] = 0ULL;

#pragma unroll 2
    for (int k = 0; k < HID; k += 4) {
        float4 bf[8];                              // warp-uniform broadcasts
#pragma unroll
        for (int j = 0; j < 8; ++j)
            bf[j] = *reinterpret_cast<const float4*>(ws + (hb + j) * HID + k);
#pragma unroll
        for (int c = 0; c < 4; ++c) {
            ulonglong2 a = *reinterpret_cast<const ulonglong2*>(
                xst + (k + c) * WSX + pb);         // lanes contiguous: 4 wf
#pragma unroll
            for (int j = 0; j < 8; ++j) {
                const float* bp = reinterpret_cast<const float*>(&bf[j]);
                u64 bb = pk2(bp[c], bp[c]);
                fma2(acc[0][j], a.x, bb);
                fma2(acc[1][j], a.y, bb);
            }
        }
    }
}

extern __shared__ float smem[];

__global__ __launch_bounds__(NT, 1)
void ffb_encoder_kernel(const float* __restrict__ in_pos,
                        const float* __restrict__ grid_feats,
                        const float* __restrict__ ffn_A,
                        const float* __restrict__ ffn_sigma,
                        const float* __restrict__ W0,
                        const float* __restrict__ b0,
                        const float* __restrict__ W_mid,
                        const float* __restrict__ b_mid,
                        const float* __restrict__ W_high,
                        const float* __restrict__ b_high,
                        float* __restrict__ out) {
    float* xst = smem;                   // HID * WSX   activations, [k][n]
    float* ws  = xst + HID * WSX;        // HID * HID   weights, flat [h][k]
    float* buf = ws + HID * HID;         // HID * WSX   high-freq acc, [h][n]
    float* gs  = buf + HID * WSX;        // TP * 14     grid feats
    float* As  = gs + TP * 14;           // LVL*2*HID   2*pi*sigma*A
    float* bms = As + LVL * 2 * HID;     // LVL * HID
    float* bhs = bms + LVL * HID;        // LVL * HID
    float* ps  = bhs + LVL * HID;        // TP * 3      positions

    const int tid  = threadIdx.x;
    const int n0   = blockIdx.x * TP;
    const int lane = tid & 31;
    const int warp = tid >> 5;           // 0..15
    const int hb   = 8 * warp;           // 8 hidden units per warp
    const int pb   = 4 * lane;           // 4 consecutive points per lane

    // ------------------------- setup: stage to SMEM -------------------------
    for (int idx = tid; idx < TP * 14; idx += NT) {
        int p = idx / 14, c = idx - p * 14;
        gs[idx] = grid_feats[(n0 + p) * 17 + 3 + c];
    }
    for (int idx = tid; idx < TP * 3; idx += NT) {
        int p = idx / 3, d = idx - p * 3;
        float v = in_pos[(n0 + p) * 3 + d];
        ps[idx] = v;
        out[(size_t)(n0 + p) * 131 + d] = (v + 1.0f) * 0.5f;   // pos01
    }
    for (int idx = tid; idx < LVL * 2 * HID; idx += NT) {
        int l = idx / (2 * HID);
        As[idx] = ffn_A[idx] * ffn_sigma[l] * TWO_PIf;
    }
    for (int idx = tid; idx < LVL * HID; idx += NT) {
        bms[idx] = b_mid[idx];
        bhs[idx] = b_high[idx];
    }
    for (int idx = tid; idx < HID * WSX; idx += NT) buf[idx] = 0.0f;
    // stage W0/b0 temporarily into ws as [h]{w0,w1,w2,b}
    if (tid < HID) {
        ws[tid * 4 + 0] = W0[tid * 3 + 0];
        ws[tid * 4 + 1] = W0[tid * 3 + 1];
        ws[tid * 4 + 2] = W0[tid * 3 + 2];
        ws[tid * 4 + 3] = b0[tid];
    }
    __syncthreads();

    // ---------------- first SIREN layer, written transposed ----------------
    {
        float px[4], py[4], pz[4];
#pragma unroll
        for (int p = 0; p < 4; ++p) {
            px[p] = ps[(pb + p) * 3 + 0];
            py[p] = ps[(pb + p) * 3 + 1];
            pz[p] = ps[(pb + p) * 3 + 2];
        }
#pragma unroll
        for (int j = 0; j < 8; ++j) {
            int h = hb + j;
            float w0 = ws[h * 4 + 0], w1 = ws[h * 4 + 1];
            float w2 = ws[h * 4 + 2], bb = ws[h * 4 + 3];
            float4 xv;
            xv.x = __sinf(W0S * fmaf(w2, pz[0], fmaf(w1, py[0], fmaf(w0, px[0], bb))));
            xv.y = __sinf(W0S * fmaf(w2, pz[1], fmaf(w1, py[1], fmaf(w0, px[1], bb))));
            xv.z = __sinf(W0S * fmaf(w2, pz[2], fmaf(w1, py[2], fmaf(w0, px[2], bb))));
            xv.w = __sinf(W0S * fmaf(w2, pz[3], fmaf(w1, py[3], fmaf(w0, px[3], bb))));
            *reinterpret_cast<float4*>(xst + h * WSX + pb) = xv;
        }
    }

    u64 acc[2][8];

    // ------------------------------ level loop -----------------------------
    for (int l = 0; l < LVL; ++l) {
        __syncthreads();                              // xst writes + ws readers
        load_weight(ws, W_mid + l * HID * HID, tid);
        __syncthreads();

        gemm_tile(xst, ws, pb, hb, acc);              // t = x @ Wm^T
        __syncthreads();                              // xst/ws reads done

        load_weight(ws, W_high + l * HID * HID, tid); // overlap with epilogue

        float A0[8], A1[8], bm8[8];
#pragma unroll
        for (int j = 0; j < 8; ++j) {
            A0[j]  = As[(2 * l) * HID + hb + j];
            A1[j]  = As[(2 * l + 1) * HID + hb + j];
            bm8[j] = bms[l * HID + hb + j];
        }
        float2 g[4];
#pragma unroll
        for (int p = 0; p < 4; ++p)
            g[p] = *reinterpret_cast<const float2*>(gs + (pb + p) * 14 + 2 * l);

#pragma unroll
        for (int j = 0; j < 8; ++j) {
            float v0, v1, v2, v3;
            upk2(acc[0][j], v0, v1);
            upk2(acc[1][j], v2, v3);
            float4 xv;
            xv.x = cw_sin(fmaf(g[0].x, A0[j], g[0].y * A1[j]))
                 + __sinf(W0S * (v0 + bm8[j]));
            xv.y = cw_sin(fmaf(g[1].x, A0[j], g[1].y * A1[j]))
                 + __sinf(W0S * (v1 + bm8[j]));
            xv.z = cw_sin(fmaf(g[2].x, A0[j], g[2].y * A1[j]))
                 + __sinf(W0S * (v2 + bm8[j]));
            xv.w = cw_sin(fmaf(g[3].x, A0[j], g[3].y * A1[j]))
                 + __sinf(W0S * (v3 + bm8[j]));
            *reinterpret_cast<float4*>(xst + (hb + j) * WSX + pb) = xv;
        }
        __syncthreads();                              // xst + ws(high) ready

        gemm_tile(xst, ws, pb, hb, acc);              // u = x @ Wh^T

        // buf[h][n] += sin(56*(u + bh)) — cell owned by exactly one thread
#pragma unroll
        for (int j = 0; j < 8; ++j) {
            float bh = bhs[l * HID + hb + j];
            float4* bp = reinterpret_cast<float4*>(buf + (hb + j) * WSX + pb);
            float4 v = *bp;
            float v0, v1, v2, v3;
            upk2(acc[0][j], v0, v1);
            upk2(acc[1][j], v2, v3);
            v.x += __sinf(W0S * (v0 + bh));
            v.y += __sinf(W0S * (v1 + bh));
            v.z += __sinf(W0S * (v2 + bh));
            v.w += __sinf(W0S * (v3 + bh));
            *bp = v;
        }
    }

    // ------------------------------- epilogue -------------------------------
    __syncthreads();
    const float inv = 1.0f / 7.0f;
    for (int idx = tid; idx < TP * HID; idx += NT) {
        int n = idx >> 7, h = idx & 127;
        out[(size_t)(n0 + n) * 131 + 3 + h] = buf[h * WSX + n] * inv;
    }
}

extern "C" void kernel_launch(void* const* d_in, const int* in_sizes, int n_in,
                              void* d_out, int out_size) {
    const float* in_pos     = (const float*)d_in[0];
    const float* grid_feats = (const float*)d_in[1];
    const float* ffn_A      = (const float*)d_in[2];
    const float* ffn_sigma  = (const float*)d_in[3];
    const float* W0         = (const float*)d_in[4];
    const float* b0         = (const float*)d_in[5];
    const float* W_mid      = (const float*)d_in[6];
    const float* b_mid      = (const float*)d_in[7];
    const float* W_high     = (const float*)d_in[8];
    const float* b_high     = (const float*)d_in[9];
    float* out = (float*)d_out;

    const int N       = in_sizes[0] / 3;   // 131072
    const int nblocks = N / TP;            // 1024

    const size_t smem_bytes =
        (size_t)(HID * WSX + HID * HID + HID * WSX + TP * 14 +
                 LVL * 2 * HID + 2 * LVL * HID + TP * 3) * sizeof(float); // ~218.5 KB

    cudaFuncSetAttribute(ffb_encoder_kernel,
                         cudaFuncAttributeMaxDynamicSharedMemorySize,
                         (int)smem_bytes);

    ffb_encoder_kernel<<<nblocks, NT, smem_bytes>>>(
        in_pos, grid_feats, ffn_A, ffn_sigma, W0, b0,
        W_mid, b_mid, W_high, b_high, out);
}